// round 2
// baseline (speedup 1.0000x reference)
#include <cuda_runtime.h>
#include <cstdint>

// Problem constants
#define PB   64
#define PT1  128
#define PT2  160
#define PD   768
#define PM   64

#define KC       32           // K chunk per smem stage
#define KSTR     36           // padded row stride in floats (36 % 32 == 4 -> conflict-free frags)
#define I_PER    2            // i rows per CTA
#define NWARP    10
#define NTHREADS 320

__device__ __forceinline__ uint32_t f2tf32(float x) {
    uint32_t r;
    asm("cvt.rna.tf32.f32 %0, %1;" : "=r"(r) : "f"(x));
    return r;
}

__device__ __forceinline__ float fast_tanh(float x) {
    float ax = fabsf(x);
    float e  = __expf(-2.0f * ax);          // EX2-based, safe for all ax >= 0
    float r  = __fdividef(1.0f - e, 1.0f + e);
    return copysignf(r, x);
}

__global__ __launch_bounds__(NTHREADS, 1)
void mpcos_kernel(const float* __restrict__ v1,
                  const float* __restrict__ v2,
                  const float* __restrict__ kern,
                  float* __restrict__ out)
{
    __shared__ float sV2[PT2 * KSTR];        // 160*36*4 = 23040 B
    __shared__ float sK [PM  * KSTR];        // 64*36*4  =  9216 B (tf32-rounded bits)
    __shared__ float sV1[I_PER * KC];        // 256 B

    const int b   = blockIdx.y;
    const int i0  = blockIdx.x * I_PER;
    const int tid = threadIdx.x;
    const int warp = tid >> 5;
    const int lane = tid & 31;
    const int qrow = lane >> 2;              // 0..7
    const int qcol = lane & 3;               // 0..3
    const int jt   = warp * 16;              // this warp's j-tile base (160 = 10*16)

    float acc[I_PER][8][4];
#pragma unroll
    for (int ii = 0; ii < I_PER; ii++)
#pragma unroll
        for (int nt = 0; nt < 8; nt++)
#pragma unroll
            for (int c = 0; c < 4; c++) acc[ii][nt][c] = 0.0f;

    const float* v2b = v2 + (size_t)b * PT2 * PD;
    const float* v1b = v1 + ((size_t)b * PT1 + i0) * PD;

    for (int k0 = 0; k0 < PD; k0 += KC) {
        __syncthreads();   // previous chunk fully consumed before overwrite

        // ---- stage v2 chunk: 160 x 32 floats (8 float4 per row) ----
        for (int t = tid; t < PT2 * (KC / 4); t += NTHREADS) {
            int j  = t >> 3;
            int c4 = (t & 7) << 2;
            float4 val = *(const float4*)(v2b + (size_t)j * PD + k0 + c4);
            *(float4*)(&sV2[j * KSTR + c4]) = val;
        }
        // ---- stage kernel chunk (round to tf32 once here): 64 x 32 ----
        for (int t = tid; t < PM * (KC / 4); t += NTHREADS) {
            int m  = t >> 3;
            int c4 = (t & 7) << 2;
            float4 val = *(const float4*)(kern + (size_t)m * PD + k0 + c4);
            val.x = __uint_as_float(f2tf32(val.x));
            val.y = __uint_as_float(f2tf32(val.y));
            val.z = __uint_as_float(f2tf32(val.z));
            val.w = __uint_as_float(f2tf32(val.w));
            *(float4*)(&sK[m * KSTR + c4]) = val;
        }
        // ---- stage v1 chunk: I_PER x 32 ----
        if (tid < I_PER * KC) {
            int ii = tid >> 5;   // KC == 32
            int c  = tid & 31;
            sV1[ii * KC + c] = v1b[(size_t)ii * PD + k0 + c];
        }
        __syncthreads();

#pragma unroll
        for (int ks = 0; ks < KC; ks += 8) {
            // v2 part of the A fragment (m16 x k8, row-major), shared across both i
            const float va0 = sV2[(jt + qrow)     * KSTR + ks + qcol];
            const float va1 = sV2[(jt + qrow + 8) * KSTR + ks + qcol];
            const float va2 = sV2[(jt + qrow)     * KSTR + ks + qcol + 4];
            const float va3 = sV2[(jt + qrow + 8) * KSTR + ks + qcol + 4];

            // B fragments (k8 x n8, col-major): kernel[m, d] with m = nt*8 + lane/4
            uint32_t bf0[8], bf1[8];
#pragma unroll
            for (int nt = 0; nt < 8; nt++) {
                bf0[nt] = __float_as_uint(sK[(nt * 8 + qrow) * KSTR + ks + qcol]);
                bf1[nt] = __float_as_uint(sK[(nt * 8 + qrow) * KSTR + ks + qcol + 4]);
            }

#pragma unroll
            for (int ii = 0; ii < I_PER; ii++) {
                const float s0 = sV1[ii * KC + ks + qcol];       // broadcast LDS
                const float s1 = sV1[ii * KC + ks + qcol + 4];
                const uint32_t a0 = f2tf32(va0 * s0);
                const uint32_t a1 = f2tf32(va1 * s0);
                const uint32_t a2 = f2tf32(va2 * s1);
                const uint32_t a3 = f2tf32(va3 * s1);
#pragma unroll
                for (int nt = 0; nt < 8; nt++) {
                    asm volatile(
                        "mma.sync.aligned.m16n8k8.row.col.f32.tf32.tf32.f32 "
                        "{%0,%1,%2,%3}, {%4,%5,%6,%7}, {%8,%9}, {%0,%1,%2,%3};"
                        : "+f"(acc[ii][nt][0]), "+f"(acc[ii][nt][1]),
                          "+f"(acc[ii][nt][2]), "+f"(acc[ii][nt][3])
                        : "r"(a0), "r"(a1), "r"(a2), "r"(a3),
                          "r"(bf0[nt]), "r"(bf1[nt]));
                }
            }
        }
    }

    // ---- epilogue: tanh + store ----
#pragma unroll
    for (int ii = 0; ii < I_PER; ii++) {
        float* ob = out + (((size_t)b * PT1 + i0 + ii) * PT2) * PM;
#pragma unroll
        for (int nt = 0; nt < 8; nt++) {
            const int col = nt * 8 + 2 * qcol;
            float2 r0, r1;
            r0.x = fast_tanh(acc[ii][nt][0]);
            r0.y = fast_tanh(acc[ii][nt][1]);
            r1.x = fast_tanh(acc[ii][nt][2]);
            r1.y = fast_tanh(acc[ii][nt][3]);
            *(float2*)(ob + (size_t)(jt + qrow)     * PM + col) = r0;
            *(float2*)(ob + (size_t)(jt + qrow + 8) * PM + col) = r1;
        }
    }
}

extern "C" void kernel_launch(void* const* d_in, const int* in_sizes, int n_in,
                              void* d_out, int out_size)
{
    // Resolve inputs by element count (all distinct): v1=6291456, v2=7864320, kernel=49152
    const float* v1 = nullptr;
    const float* v2 = nullptr;
    const float* kern = nullptr;
    for (int idx = 0; idx < n_in; idx++) {
        if (in_sizes[idx] == PB * PT1 * PD)      v1   = (const float*)d_in[idx];
        else if (in_sizes[idx] == PB * PT2 * PD) v2   = (const float*)d_in[idx];
        else if (in_sizes[idx] == PM * PD)       kern = (const float*)d_in[idx];
    }
    float* out = (float*)d_out;

    dim3 grid(PT1 / I_PER, PB);   // (64, 64): x-fastest keeps same-b CTAs co-resident for L2 reuse of v2
    mpcos_kernel<<<grid, NTHREADS>>>(v1, v2, kern, out);
}

// round 4
// speedup vs baseline: 2.2010x; 2.2010x over previous
#include <cuda_runtime.h>
#include <cstdint>

// out[b,i,j,m] = tanh( sum_d v1[b,i,d] * kernel[m,d] * v2[b,j,d] )
#define PB   64
#define PT1  128
#define PT2  160
#define PD   768
#define PM   64

#define KC       32                  // K per chunk
#define NCHUNK   (PD / KC)           // 24
#define NS       3                   // pipeline stages
#define NT       640                 // threads (20 warps)
#define I_PER    2

#define V2STR    144                 // bytes per v2 smem row (36 floats, conflict-free)
#define STG_V2   (PT2 * V2STR)       // 23040
#define KP_CHUNK_F2 1088             // float2 per kernel chunk: 4 slices * 4 qcol * 68
#define STG_KP   (KP_CHUNK_F2 * 8)   // 8704 bytes
#define STGB     (STG_V2 + STG_KP)   // 31744
#define V1_BYTES (I_PER * PD * 4)    // 6144
#define SMEM_TOTAL (V1_BYTES + NS * STGB)   // 101376

// Pre-rounded, fragment-permuted kernel weights (tf32 bits as float)
__device__ __align__(16) float2 g_kperm[NCHUNK * KP_CHUNK_F2];

__device__ __forceinline__ uint32_t f2tf32(float x) {
    uint32_t r; asm("cvt.rna.tf32.f32 %0, %1;" : "=r"(r) : "f"(x)); return r;
}
__device__ __forceinline__ float fast_tanh(float x) {
    float ax = fabsf(x);
    float e  = __expf(-2.0f * ax);
    float r  = __fdividef(1.0f - e, 1.0f + e);
    return copysignf(r, x);
}
__device__ __forceinline__ uint32_t s2u(const void* p) {
    uint32_t a;
    asm("{ .reg .u64 t; cvta.to.shared.u64 t, %1; cvt.u32.u64 %0, t; }" : "=r"(a) : "l"(p));
    return a;
}
__device__ __forceinline__ void cpa16(uint32_t dst, const void* src) {
    asm volatile("cp.async.cg.shared.global [%0], [%1], 16;" :: "r"(dst), "l"(src));
}

// ---- pre-kernel: tf32-round weights into fragment-permuted layout ----
// slot(c, s, qc, m) = c*1088 + (s*4+qc)*68 + m   (float2 = {k[m][d], k[m][d+4]}, d = c*32+s*8+qc)
__global__ void prep_kernel(const float* __restrict__ kern) {
    int t = blockIdx.x * blockDim.x + threadIdx.x;
    if (t >= PM * NCHUNK * 16) return;
    int m  = t & 63;
    int r  = t >> 6;            // c*16 + s*4 + qc
    int c  = r >> 4;
    int s  = (r >> 2) & 3;
    int qc = r & 3;
    int d  = c * KC + s * 8 + qc;
    float2 p;
    p.x = __uint_as_float(f2tf32(kern[m * PD + d]));
    p.y = __uint_as_float(f2tf32(kern[m * PD + d + 4]));
    g_kperm[c * KP_CHUNK_F2 + (s * 4 + qc) * 68 + m] = p;
}

__device__ __forceinline__ void prefetch_stage(uint32_t stg, const float* v2b, int c, int tid) {
    // v2 raw chunk: 160 rows x 128B  (1280 x 16B)
#pragma unroll
    for (int it = 0; it < 2; it++) {
        int t   = tid + it * NT;
        int row = t >> 3, q = t & 7;
        cpa16(stg + row * V2STR + q * 16,
              (const char*)(v2b + (size_t)row * PD + c * KC) + q * 16);
    }
    // permuted kernel chunk: contiguous 8704B (544 x 16B)
    if (tid < STG_KP / 16) {
        cpa16(stg + STG_V2 + tid * 16,
              (const char*)(g_kperm + c * KP_CHUNK_F2) + tid * 16);
    }
}

extern __shared__ char dynsmem[];

__global__ __launch_bounds__(NT, 1)
void mpcos_main(const float* __restrict__ v1, const float* __restrict__ v2,
                float* __restrict__ out)
{
    const uint32_t sb = s2u(dynsmem);
    const float* v1sh = (const float*)dynsmem;

    const int tid  = threadIdx.x;
    const int w    = tid >> 5, lane = tid & 31;
    const int qrow = lane >> 2, qcol = lane & 3;
    const int jw   = w % 10, mw = w / 10;     // j-tile (16 rows), m-half (32 cols)
    const int jt   = jw * 16;
    const int b    = blockIdx.y;
    const int i0   = blockIdx.x * I_PER;

    const float* v2b = v2 + (size_t)b * PT2 * PD;
    const float* v1b = v1 + ((size_t)b * PT1 + i0) * PD;

    // ---- prologue: v1 (whole) + first NS-1 chunks via cp.async ----
    if (tid < V1_BYTES / 16)
        cpa16(sb + tid * 16, (const char*)v1b + tid * 16);
    prefetch_stage(sb + V1_BYTES, v2b, 0, tid);
    asm volatile("cp.async.commit_group;" ::: "memory");
    prefetch_stage(sb + V1_BYTES + STGB, v2b, 1, tid);
    asm volatile("cp.async.commit_group;" ::: "memory");

    float acc[I_PER][4][4] = {};

    // stage-relative fragment offsets
    const uint32_t aoff = (uint32_t)((jt + qrow) * V2STR + qcol * 4);
    const uint32_t boff = (uint32_t)(STG_V2 + (qcol * 68 + mw * 32 + qrow) * 8);

    for (int c = 0; c < NCHUNK; c++) {
        asm volatile("cp.async.wait_group 1;" ::: "memory");
        __syncthreads();

        const int pc = c + NS - 1;
        if (pc < NCHUNK)
            prefetch_stage(sb + V1_BYTES + (pc % NS) * STGB, v2b, pc, tid);
        asm volatile("cp.async.commit_group;" ::: "memory");

        const char* stg = dynsmem + V1_BYTES + (c % NS) * STGB;
        const int k0 = c * KC;

#pragma unroll
        for (int ks = 0; ks < 4; ks++) {          // K slices of 8
            // A fragments: raw v2
            const char* ap = stg + aoff + ks * 32;
            const float va0 = *(const float*)(ap);
            const float va1 = *(const float*)(ap + 8 * V2STR);
            const float va2 = *(const float*)(ap + 16);
            const float va3 = *(const float*)(ap + 8 * V2STR + 16);

            // B fragments: pre-rounded kernel, one LDS.64 each, conflict-free
            const char* bp = stg + boff + ks * 2176;
            float2 bf0 = *(const float2*)(bp);
            float2 bf1 = *(const float2*)(bp + 64);
            float2 bf2 = *(const float2*)(bp + 128);
            float2 bf3 = *(const float2*)(bp + 192);

#pragma unroll
            for (int ii = 0; ii < I_PER; ii++) {
                const float s0 = v1sh[ii * PD + k0 + ks * 8 + qcol];
                const float s1 = v1sh[ii * PD + k0 + ks * 8 + qcol + 4];
                const uint32_t a0 = f2tf32(va0 * s0);
                const uint32_t a1 = f2tf32(va1 * s0);
                const uint32_t a2 = f2tf32(va2 * s1);
                const uint32_t a3 = f2tf32(va3 * s1);
#define DO_MMA(nt, BF)                                                          \
                asm volatile(                                                   \
                    "mma.sync.aligned.m16n8k8.row.col.f32.tf32.tf32.f32 "      \
                    "{%0,%1,%2,%3}, {%4,%5,%6,%7}, {%8,%9}, {%0,%1,%2,%3};"    \
                    : "+f"(acc[ii][nt][0]), "+f"(acc[ii][nt][1]),              \
                      "+f"(acc[ii][nt][2]), "+f"(acc[ii][nt][3])               \
                    : "r"(a0), "r"(a1), "r"(a2), "r"(a3),                      \
                      "r"(__float_as_uint(BF.x)), "r"(__float_as_uint(BF.y)))
                DO_MMA(0, bf0);
                DO_MMA(1, bf1);
                DO_MMA(2, bf2);
                DO_MMA(3, bf3);
#undef DO_MMA
            }
        }
    }

    // ---- epilogue: tanh + store ----
#pragma unroll
    for (int ii = 0; ii < I_PER; ii++) {
        float* ob = out + ((size_t)(b * PT1 + i0 + ii) * PT2) * PM;
#pragma unroll
        for (int nt = 0; nt < 4; nt++) {
            const int col = mw * 32 + nt * 8 + 2 * qcol;
            float2 r0, r1;
            r0.x = fast_tanh(acc[ii][nt][0]);
            r0.y = fast_tanh(acc[ii][nt][1]);
            r1.x = fast_tanh(acc[ii][nt][2]);
            r1.y = fast_tanh(acc[ii][nt][3]);
            *(float2*)(ob + (size_t)(jt + qrow)     * PM + col) = r0;
            *(float2*)(ob + (size_t)(jt + qrow + 8) * PM + col) = r1;
        }
    }
}

extern "C" void kernel_launch(void* const* d_in, const int* in_sizes, int n_in,
                              void* d_out, int out_size)
{
    const float* v1 = nullptr;
    const float* v2 = nullptr;
    const float* kern = nullptr;
    for (int idx = 0; idx < n_in; idx++) {
        if (in_sizes[idx] == PB * PT1 * PD)      v1   = (const float*)d_in[idx];
        else if (in_sizes[idx] == PB * PT2 * PD) v2   = (const float*)d_in[idx];
        else if (in_sizes[idx] == PM * PD)       kern = (const float*)d_in[idx];
    }
    float* out = (float*)d_out;

    prep_kernel<<<(PM * NCHUNK * 16 + 255) / 256, 256>>>(kern);

    cudaFuncSetAttribute(mpcos_main, cudaFuncAttributeMaxDynamicSharedMemorySize, SMEM_TOTAL);
    dim3 grid(PT1 / I_PER, PB);   // (64, 64)
    mpcos_main<<<grid, NT, SMEM_TOTAL>>>(v1, v2, out);
}

// round 6
// speedup vs baseline: 2.9062x; 1.3204x over previous
#include <cuda_runtime.h>
#include <cstdint>

// out[b,i,j,m] = tanh( sum_d v1[b,i,d] * kernel[m,d] * v2[b,j,d] )
#define PB   64
#define PT1  128
#define PT2  160
#define PD   768
#define PM   64

#define KC       32                   // K per chunk
#define NCHUNK   (PD / KC)            // 24
#define NS       3                    // pipeline stages
#define NT       320                  // 10 warps
#define I_PER    2

#define PAIR_STR  320                 // bytes per v2 row-pair (256B data + 64B pad)
#define STG_V2    (80 * PAIR_STR)     // 25600
#define STG_KP    8704                // kernel chunk (68-f2 stride x 16 slices)
#define STGB      (STG_V2 + STG_KP)   // 34304
#define V1P_BYTES 6144                // 768 float2 pairs
#define SMEM_TOTAL (V1P_BYTES + NS * STGB)   // 109056

// ---- device-global prepped operands ----
// v2 permuted: per (b,c): 80 row-pairs x 16 float4 {v2[j][d], v2[j][d+4], v2[j+8][d], v2[j+8][d+4]}
__device__ __align__(16) float4 g_v2p[PB * NCHUNK * 1280];
// kernel tf32-rounded, fragment-permuted: slot(c, ks, qc, m) = c*1088 + (ks*4+qc)*68 + m
__device__ __align__(16) float2 g_kperm[NCHUNK * 1088];

__device__ __forceinline__ uint32_t f2tf32(float x) {
    uint32_t r; asm("cvt.rna.tf32.f32 %0, %1;" : "=r"(r) : "f"(x)); return r;
}
__device__ __forceinline__ float fast_tanh(float x) {
    float ax = fabsf(x);
    float e  = __expf(-2.0f * ax);
    float r  = __fdividef(1.0f - e, 1.0f + e);
    return copysignf(r, x);
}
__device__ __forceinline__ uint32_t s2u(const void* p) {
    uint32_t a;
    asm("{ .reg .u64 t; cvta.to.shared.u64 t, %1; cvt.u32.u64 %0, t; }" : "=r"(a) : "l"(p));
    return a;
}
__device__ __forceinline__ void cpa16(uint32_t dst, const void* src) {
    asm volatile("cp.async.cg.shared.global [%0], [%1], 16;" :: "r"(dst), "l"(src));
}

// ---- prep: tf32-round kernel into fragment-permuted layout ----
__global__ void prep_kernel(const float* __restrict__ kern) {
    int t = blockIdx.x * blockDim.x + threadIdx.x;
    if (t >= PM * NCHUNK * 16) return;
    int m  = t & 63;
    int r  = t >> 6;            // c*16 + ks*4 + qc
    int c  = r >> 4;
    int ks = (r >> 2) & 3;
    int qc = r & 3;
    int d  = c * KC + ks * 8 + qc;
    float2 p;
    p.x = __uint_as_float(f2tf32(kern[m * PD + d]));
    p.y = __uint_as_float(f2tf32(kern[m * PD + d + 4]));
    g_kperm[c * 1088 + (ks * 4 + qc) * 68 + m] = p;
}

// ---- prep: permute v2 into A-fragment float4 layout ----
__global__ void prep_v2(const float* __restrict__ v2) {
    int t = blockIdx.x * blockDim.x + threadIdx.x;
    if (t >= PB * NCHUNK * 1280) return;
    int q  = t & 15;
    int pr = (t >> 4) % 80;
    int c  = ((t >> 4) / 80) % NCHUNK;
    int b  = (t >> 4) / (80 * NCHUNK);
    int j  = (pr >> 3) * 16 + (pr & 7);
    int d  = c * KC + (q >> 2) * 8 + (q & 3);
    const float* base = v2 + ((size_t)(b * PT2 + j) * PD + d);
    g_v2p[t] = make_float4(base[0], base[4], base[8 * PD], base[8 * PD + 4]);
}

extern __shared__ char dynsmem[];

__device__ __forceinline__ void prefetch_stage(uint32_t stg, const float4* v2src,
                                               const float2* ksrc, int tid) {
#pragma unroll
    for (int it = 0; it < 4; it++) {               // 1280 float4
        int t  = tid + it * NT;
        int pr = t >> 4, q = t & 15;
        cpa16(stg + pr * PAIR_STR + q * 16, v2src + t);
    }
    for (int t = tid; t < STG_KP / 16; t += NT)    // 544 x 16B, contiguous
        cpa16(stg + STG_V2 + t * 16, (const char*)ksrc + t * 16);
}

__global__ __launch_bounds__(NT, 2)
void mpcos_main(const float* __restrict__ v1, float* __restrict__ out)
{
    const uint32_t sb = s2u(dynsmem);
    const int tid  = threadIdx.x;
    const int w    = tid >> 5, lane = tid & 31;
    const int qrow = lane >> 2, qcol = lane & 3;
    const int jt   = w * 16;                        // warp's j-tile (10 warps x 16 = 160)
    const int b    = blockIdx.y;
    const int i0   = blockIdx.x * I_PER;

    const float* v1b = v1 + ((size_t)b * PT1 + i0) * PD;

    // ---- build v1 pair table: idx = ii*384 + c*16 + qc*4 + ks -> {v1[d], v1[d+4]} ----
    for (int t = tid; t < I_PER * 384; t += NT) {
        int ii = t / 384;                 // (NOT t>>something: 384 isn't a power of 2)
        int r  = t % 384;
        int c  = r >> 4, qc = (r >> 2) & 3, ks = r & 3;
        int d  = c * KC + ks * 8 + qc;
        float2 p;
        p.x = __ldg(v1b + (size_t)ii * PD + d);
        p.y = __ldg(v1b + (size_t)ii * PD + d + 4);
        *(float2*)(dynsmem + (size_t)t * 8) = p;
    }

    const float4* v2src = g_v2p + (size_t)b * NCHUNK * 1280;
    prefetch_stage(sb + V1P_BYTES, v2src, g_kperm, tid);
    asm volatile("cp.async.commit_group;" ::: "memory");
    prefetch_stage(sb + V1P_BYTES + STGB, v2src + 1280, g_kperm + 1088, tid);
    asm volatile("cp.async.commit_group;" ::: "memory");

    float acc[I_PER][8][4] = {};

    const uint32_t aoff = (uint32_t)((w * 8 + qrow) * PAIR_STR + qcol * 16);
    const uint32_t boff = (uint32_t)(STG_V2 + qcol * 68 * 8 + qrow * 8);

    for (int c = 0; c < NCHUNK; c++) {
        asm volatile("cp.async.wait_group 1;" ::: "memory");
        __syncthreads();

        const int pc = c + NS - 1;
        if (pc < NCHUNK)
            prefetch_stage(sb + V1P_BYTES + (pc % NS) * STGB,
                           v2src + (size_t)pc * 1280, g_kperm + pc * 1088, tid);
        asm volatile("cp.async.commit_group;" ::: "memory");

        const char* stg = dynsmem + V1P_BYTES + (c % NS) * STGB;
        const int vbase = c * 16 + qcol * 4;        // float2 index into v1 pair table

#pragma unroll
        for (int ks = 0; ks < 4; ks++) {
            // A fragment raw: one LDS.128 {x=v2[j][d], y=[j][d+4], z=[j+8][d], w=[j+8][d+4]}
            const float4 va = *(const float4*)(stg + aoff + ks * 64);
            // v1 pairs (broadcast LDS.64)
            const float2 s0 = *(const float2*)(dynsmem + (size_t)(vbase + ks) * 8);
            const float2 s1 = *(const float2*)(dynsmem + (size_t)(384 + vbase + ks) * 8);

            uint32_t a[I_PER][4];
            a[0][0] = f2tf32(va.x * s0.x);
            a[0][1] = f2tf32(va.z * s0.x);
            a[0][2] = f2tf32(va.y * s0.y);
            a[0][3] = f2tf32(va.w * s0.y);
            a[1][0] = f2tf32(va.x * s1.x);
            a[1][1] = f2tf32(va.z * s1.x);
            a[1][2] = f2tf32(va.y * s1.y);
            a[1][3] = f2tf32(va.w * s1.y);

            const char* bb = stg + boff + ks * (4 * 68 * 8);
#pragma unroll
            for (int nt = 0; nt < 8; nt++) {
                const float2 bf = *(const float2*)(bb + nt * 64);
                const uint32_t b0 = __float_as_uint(bf.x);
                const uint32_t b1 = __float_as_uint(bf.y);
#pragma unroll
                for (int ii = 0; ii < I_PER; ii++) {
                    asm volatile(
                        "mma.sync.aligned.m16n8k8.row.col.f32.tf32.tf32.f32 "
                        "{%0,%1,%2,%3}, {%4,%5,%6,%7}, {%8,%9}, {%0,%1,%2,%3};"
                        : "+f"(acc[ii][nt][0]), "+f"(acc[ii][nt][1]),
                          "+f"(acc[ii][nt][2]), "+f"(acc[ii][nt][3])
                        : "r"(a[ii][0]), "r"(a[ii][1]), "r"(a[ii][2]), "r"(a[ii][3]),
                          "r"(b0), "r"(b1));
                }
            }
        }
    }

    // ---- epilogue: tanh + store ----
#pragma unroll
    for (int ii = 0; ii < I_PER; ii++) {
        float* ob = out + ((size_t)(b * PT1 + i0 + ii) * PT2) * PM;
#pragma unroll
        for (int nt = 0; nt < 8; nt++) {
            const int col = nt * 8 + 2 * qcol;
            float2 r0, r1;
            r0.x = fast_tanh(acc[ii][nt][0]);
            r0.y = fast_tanh(acc[ii][nt][1]);
            r1.x = fast_tanh(acc[ii][nt][2]);
            r1.y = fast_tanh(acc[ii][nt][3]);
            *(float2*)(ob + (size_t)(jt + qrow)     * PM + col) = r0;
            *(float2*)(ob + (size_t)(jt + qrow + 8) * PM + col) = r1;
        }
    }
}

extern "C" void kernel_launch(void* const* d_in, const int* in_sizes, int n_in,
                              void* d_out, int out_size)
{
    const float* v1 = nullptr;
    const float* v2 = nullptr;
    const float* kern = nullptr;
    for (int idx = 0; idx < n_in; idx++) {
        if (in_sizes[idx] == PB * PT1 * PD)      v1   = (const float*)d_in[idx];
        else if (in_sizes[idx] == PB * PT2 * PD) v2   = (const float*)d_in[idx];
        else if (in_sizes[idx] == PM * PD)       kern = (const float*)d_in[idx];
    }
    float* out = (float*)d_out;

    prep_kernel<<<(PM * NCHUNK * 16 + 255) / 256, 256>>>(kern);
    prep_v2<<<(PB * NCHUNK * 1280 + 255) / 256, 256>>>(v2);

    cudaFuncSetAttribute(mpcos_main, cudaFuncAttributeMaxDynamicSharedMemorySize, SMEM_TOTAL);
    dim3 grid(PT1 / I_PER, PB);   // (64, 64)
    mpcos_main<<<grid, NT, SMEM_TOTAL>>>(v1, out);
}

// round 7
// speedup vs baseline: 2.9314x; 1.0087x over previous
#include <cuda_runtime.h>
#include <cstdint>

// out[b,i,j,m] = tanh( sum_d v1[b,i,d] * kernel[m,d] * v2[b,j,d] )
#define PB   64
#define PT1  128
#define PT2  160
#define PD   768
#define PM   64

#define NSLICE   96                   // 8-wide k-slices
#define KSC      6                    // slices per chunk (KC=48)
#define NCHUNK   (NSLICE / KSC)       // 16
#define NT       320                  // 10 warps
#define I_PER    2

#define PAIR_STR  448                 // bytes per v2 row-pair in smem (384B data + 64B pad)
#define STG_V2    (80 * PAIR_STR)     // 35840
#define SLICE_KB  2176                // kernel bytes per slice (4qc x 68 f2)
#define STG_KP    (KSC * SLICE_KB)    // 13056
#define STGB      (STG_V2 + STG_KP)   // 48896
#define V1P_BYTES 6144                // 2 x 384 float2
#define SMEM_TOTAL (V1P_BYTES + 2 * STGB)   // 103936

#define V2N (PB * NSLICE * 80 * 4)    // 1966080 float4
#define KPN (NSLICE * 4 * PM)         // 24576 float2 slots

// ---- device-global prepped operands ----
// g_v2p[((b*96+s)*80+pr)*4+q] = {v2[j][d], v2[j][d+4], v2[j+8][d], v2[j+8][d+4]},
//   j = (pr>>3)*16 + (pr&7), d = s*8+q
__device__ __align__(16) float4 g_v2p[V2N];
// g_kperm[s*272 + qc*68 + m] = {tf32(k[m][s*8+qc]), tf32(k[m][s*8+qc+4])}
__device__ __align__(16) float2 g_kperm[NSLICE * 272];

__device__ __forceinline__ uint32_t f2tf32(float x) {
    uint32_t r; asm("cvt.rna.tf32.f32 %0, %1;" : "=r"(r) : "f"(x)); return r;
}
__device__ __forceinline__ float fast_tanh(float x) {
    float ax = fabsf(x);
    float e  = __expf(-2.0f * ax);
    float r  = __fdividef(1.0f - e, 1.0f + e);
    return copysignf(r, x);
}
__device__ __forceinline__ uint32_t s2u(const void* p) {
    uint32_t a;
    asm("{ .reg .u64 t; cvta.to.shared.u64 t, %1; cvt.u32.u64 %0, t; }" : "=r"(a) : "l"(p));
    return a;
}
__device__ __forceinline__ void cpa16(uint32_t dst, const void* src) {
    asm volatile("cp.async.cg.shared.global [%0], [%1], 16;" :: "r"(dst), "l"(src));
}

// ---- merged prep: permute v2 + tf32-round kernel ----
__global__ void prep_all(const float* __restrict__ v2, const float* __restrict__ kern) {
    int t = blockIdx.x * blockDim.x + threadIdx.x;
    if (t < V2N) {
        int q  = t & 3;
        int r  = t >> 2;
        int pr = r % 80;
        int s  = (r / 80) % NSLICE;
        int b  = r / (80 * NSLICE);
        int j  = (pr >> 3) * 16 + (pr & 7);
        int d  = s * 8 + q;
        const float* base = v2 + ((size_t)(b * PT2 + j) * PD + d);
        g_v2p[t] = make_float4(base[0], base[4], base[8 * PD], base[8 * PD + 4]);
    } else if (t < V2N + KPN) {
        int u  = t - V2N;
        int m  = u & 63;
        int qc = (u >> 6) & 3;
        int s  = u >> 8;
        int d  = s * 8 + qc;
        float2 p;
        p.x = __uint_as_float(f2tf32(kern[m * PD + d]));
        p.y = __uint_as_float(f2tf32(kern[m * PD + d + 4]));
        g_kperm[s * 272 + qc * 68 + m] = p;
    }
}

extern __shared__ char dynsmem[];

// stage one chunk (6 slices): v2 pairs (1920 float4) + kernel (816 x 16B)
__device__ __forceinline__ void prefetch_stage(uint32_t stg, const float4* v2b4,
                                               int s0, int tid) {
#pragma unroll
    for (int it = 0; it < 6; it++) {               // 1920 float4
        int t  = tid + it * NT;
        int pr = t / 24, r = t % 24;               // r = s'*4 + q
        int sp = r >> 2, q = r & 3;
        cpa16(stg + pr * PAIR_STR + r * 16,
              v2b4 + ((size_t)(s0 + sp) * 80 + pr) * 4 + q);
    }
    const char* ksrc = (const char*)(g_kperm + (size_t)s0 * 272);
#pragma unroll
    for (int it = 0; it < 3; it++) {               // 816 x 16B (last iter partial)
        int t = tid + it * NT;
        if (t < STG_KP / 16)
            cpa16(stg + STG_V2 + t * 16, ksrc + t * 16);
    }
}

__global__ __launch_bounds__(NT, 2)
void mpcos_main(const float* __restrict__ v1, float* __restrict__ out)
{
    const uint32_t sb = s2u(dynsmem);
    const int tid  = threadIdx.x;
    const int w    = tid >> 5, lane = tid & 31;
    const int qrow = lane >> 2, qcol = lane & 3;
    const int jt   = w * 16;                        // warp's j-tile
    const int b    = blockIdx.y;
    const int i0   = blockIdx.x * I_PER;

    const float* v1b = v1 + ((size_t)b * PT1 + i0) * PD;

    // ---- v1 pair table: idx = ii*384 + s*4 + qc -> {v1[d], v1[d+4]}, d = s*8+qc ----
    for (int t = tid; t < I_PER * 384; t += NT) {
        int ii = t / 384;
        int r  = t - ii * 384;
        int s  = r >> 2, qc = r & 3;
        int d  = s * 8 + qc;
        float2 p;
        p.x = __ldg(v1b + (size_t)ii * PD + d);
        p.y = __ldg(v1b + (size_t)ii * PD + d + 4);
        *(float2*)(dynsmem + (size_t)t * 8) = p;
    }

    const float4* v2b4 = g_v2p + (size_t)b * NSLICE * 80 * 4;
    prefetch_stage(sb + V1P_BYTES, v2b4, 0, tid);
    asm volatile("cp.async.commit_group;" ::: "memory");

    float acc[I_PER][8][4] = {};

    const uint32_t aoff = (uint32_t)((w * 8 + qrow) * PAIR_STR + qcol * 16);
    const uint32_t boff = (uint32_t)(STG_V2 + qcol * 544 + qrow * 8);

    for (int c = 0; c < NCHUNK; c++) {
        asm volatile("cp.async.wait_group 0;" ::: "memory");   // chunk c arrived
        __syncthreads();                                       // chunk c-1 fully consumed

        if (c + 1 < NCHUNK) {
            prefetch_stage(sb + V1P_BYTES + ((c + 1) & 1) * STGB, v2b4, (c + 1) * KSC, tid);
            asm volatile("cp.async.commit_group;" ::: "memory");
        }

        const char* stg = dynsmem + V1P_BYTES + (c & 1) * STGB;
        const int vbase = c * KSC * 4 + qcol;       // f2 index step of 4 per slice

#pragma unroll
        for (int ks = 0; ks < KSC; ks++) {
            // A fragment: one LDS.128 {v2[j][d], v2[j][d+4], v2[j+8][d], v2[j+8][d+4]}
            const float4 va = *(const float4*)(stg + aoff + ks * 64);
            // v1 pairs (broadcast LDS.64)
            const float2 s0 = *(const float2*)(dynsmem + (size_t)(vbase + ks * 4) * 8);
            const float2 s1 = *(const float2*)(dynsmem + (size_t)(384 + vbase + ks * 4) * 8);

            uint32_t a[I_PER][4];
            a[0][0] = f2tf32(va.x * s0.x);
            a[0][1] = f2tf32(va.z * s0.x);
            a[0][2] = f2tf32(va.y * s0.y);
            a[0][3] = f2tf32(va.w * s0.y);
            a[1][0] = f2tf32(va.x * s1.x);
            a[1][1] = f2tf32(va.z * s1.x);
            a[1][2] = f2tf32(va.y * s1.y);
            a[1][3] = f2tf32(va.w * s1.y);

            const char* bb = stg + boff + ks * SLICE_KB;
#pragma unroll
            for (int nt = 0; nt < 8; nt++) {
                const float2 bf = *(const float2*)(bb + nt * 64);
                const uint32_t b0 = __float_as_uint(bf.x);
                const uint32_t b1 = __float_as_uint(bf.y);
#pragma unroll
                for (int ii = 0; ii < I_PER; ii++) {
                    asm volatile(
                        "mma.sync.aligned.m16n8k8.row.col.f32.tf32.tf32.f32 "
                        "{%0,%1,%2,%3}, {%4,%5,%6,%7}, {%8,%9}, {%0,%1,%2,%3};"
                        : "+f"(acc[ii][nt][0]), "+f"(acc[ii][nt][1]),
                          "+f"(acc[ii][nt][2]), "+f"(acc[ii][nt][3])
                        : "r"(a[ii][0]), "r"(a[ii][1]), "r"(a[ii][2]), "r"(a[ii][3]),
                          "r"(b0), "r"(b1));
                }
            }
        }
    }

    // ---- epilogue: tanh + store ----
#pragma unroll
    for (int ii = 0; ii < I_PER; ii++) {
        float* ob = out + ((size_t)(b * PT1 + i0 + ii) * PT2) * PM;
#pragma unroll
        for (int nt = 0; nt < 8; nt++) {
            const int col = nt * 8 + 2 * qcol;
            float2 r0, r1;
            r0.x = fast_tanh(acc[ii][nt][0]);
            r0.y = fast_tanh(acc[ii][nt][1]);
            r1.x = fast_tanh(acc[ii][nt][2]);
            r1.y = fast_tanh(acc[ii][nt][3]);
            *(float2*)(ob + (size_t)(jt + qrow)     * PM + col) = r0;
            *(float2*)(ob + (size_t)(jt + qrow + 8) * PM + col) = r1;
        }
    }
}

extern "C" void kernel_launch(void* const* d_in, const int* in_sizes, int n_in,
                              void* d_out, int out_size)
{
    const float* v1 = nullptr;
    const float* v2 = nullptr;
    const float* kern = nullptr;
    for (int idx = 0; idx < n_in; idx++) {
        if (in_sizes[idx] == PB * PT1 * PD)      v1   = (const float*)d_in[idx];
        else if (in_sizes[idx] == PB * PT2 * PD) v2   = (const float*)d_in[idx];
        else if (in_sizes[idx] == PM * PD)       kern = (const float*)d_in[idx];
    }
    float* out = (float*)d_out;

    prep_all<<<(V2N + KPN + 255) / 256, 256>>>(v2, kern);

    cudaFuncSetAttribute(mpcos_main, cudaFuncAttributeMaxDynamicSharedMemorySize, SMEM_TOTAL);
    dim3 grid(PT1 / I_PER, PB);   // (64, 64)
    mpcos_main<<<grid, NT, SMEM_TOTAL>>>(v1, out);
}

// round 10
// speedup vs baseline: 5.1291x; 1.7497x over previous
#include <cuda_runtime.h>
#include <cuda_fp16.h>
#include <cstdint>

// out[b,i,j,m] = tanh( sum_d v1[b,i,d] * kernel[m,d] * v2[b,j,d] )
#define PB   64
#define PT1  128
#define PT2  160
#define PD   768
#define PM   64

#define NS16     48                   // 16-wide k-slices
#define KSC      3                    // slices per chunk (K=48)
#define NCHUNK   (NS16 / KSC)         // 16
#define NS       3                    // pipeline stages
#define NT       320                  // 10 warps
#define I_PER    2

#define PRSTR    192                  // bytes per v2 pair-row per chunk (conflict-free LDS.128)
#define STG_V2   (80 * PRSTR)         // 15360
#define SLICE_KB 2176                 // kernel bytes per k16 slice (4 qc x 544)
#define STG_KP   (KSC * SLICE_KB)     // 6528
#define STGB     (STG_V2 + STG_KP)    // 21888
#define V1T      3072                 // v1 table: 2 ii x 192 float2
#define SMEM_TOTAL (V1T + NS * STGB)  // 68736

#define V2HN (PB * 80 * NS16 * 4)     // 983040 float4 entries
#define KHN  (NS16 * 4 * PM)          // 12288 float2 slots

// ---- device-global fp16-prepped operands ----
// g_v2h[((b*80+pr)*48+s)*4+qc] = 8 fp16:
//   {h2(v2[j][d0],v2[j][d0+1]), h2(v2[j8][d0],v2[j8][d0+1]),
//    h2(v2[j][d0+8],v2[j][d0+9]), h2(v2[j8][d0+8],v2[j8][d0+9])}
//   j = (pr>>3)*16 + (pr&7), j8 = j+8, d0 = s*16 + 2*qc
__device__ __align__(16) float4 g_v2h[V2HN];
// g_kh[s*272 + qc*68 + m] = {h2(k[m][d0],k[m][d0+1]), h2(k[m][d0+8],k[m][d0+9])}
__device__ __align__(16) float2 g_kh[NS16 * 272];

__device__ __forceinline__ float fast_tanh(float x) {
    float ax = fabsf(x);
    float e  = __expf(-2.0f * ax);
    float r  = __fdividef(1.0f - e, 1.0f + e);
    return copysignf(r, x);
}
__device__ __forceinline__ uint32_t s2u(const void* p) {
    uint32_t a;
    asm("{ .reg .u64 t; cvta.to.shared.u64 t, %1; cvt.u32.u64 %0, t; }" : "=r"(a) : "l"(p));
    return a;
}
__device__ __forceinline__ void cpa16(uint32_t dst, const void* src) {
    asm volatile("cp.async.cg.shared.global [%0], [%1], 16;" :: "r"(dst), "l"(src));
}
__device__ __forceinline__ uint32_t h2pack(float x, float y) {
    __half2 h = __floats2half2_rn(x, y);
    return *(uint32_t*)&h;
}
__device__ __forceinline__ uint32_t hmul2(uint32_t a, uint32_t b) {
    uint32_t d;
    asm("mul.rn.f16x2 %0, %1, %2;" : "=r"(d) : "r"(a), "r"(b));
    return d;
}

// ---- prep: fp16-convert + permute v2 and kernel ----
__global__ void prep_all(const float* __restrict__ v2, const float* __restrict__ kern) {
    int t = blockIdx.x * blockDim.x + threadIdx.x;
    if (t < V2HN) {
        int qc = t & 3;
        int t2 = t >> 2;
        int s  = t2 % NS16;
        int pr = (t2 / NS16) % 80;
        int b  = t2 / (NS16 * 80);
        int j  = (pr >> 3) * 16 + (pr & 7);
        int d0 = s * 16 + 2 * qc;
        const float* p0 = v2 + ((size_t)(b * PT2 + j) * PD + d0);
        const float* p8 = p0 + 8 * PD;
        float4 o;
        o.x = __uint_as_float(h2pack(p0[0], p0[1]));
        o.y = __uint_as_float(h2pack(p8[0], p8[1]));
        o.z = __uint_as_float(h2pack(p0[8], p0[9]));
        o.w = __uint_as_float(h2pack(p8[8], p8[9]));
        g_v2h[t] = o;
    } else if (t < V2HN + KHN) {
        int u  = t - V2HN;
        int m  = u & 63;
        int qc = (u >> 6) & 3;
        int s  = u >> 8;
        int d0 = s * 16 + 2 * qc;
        const float* kp = kern + (size_t)m * PD + d0;
        float2 o;
        o.x = __uint_as_float(h2pack(kp[0], kp[1]));
        o.y = __uint_as_float(h2pack(kp[8], kp[9]));
        g_kh[s * 272 + qc * 68 + m] = o;
    }
}

extern __shared__ char dynsmem[];

// stage one chunk (3 k16 slices): v2 960 float4 + kernel 408 x 16B
__device__ __forceinline__ void prefetch_stage(uint32_t stg, int b, int s0, int tid) {
#pragma unroll
    for (int it = 0; it < 3; it++) {               // 960 = 3 * NT
        int t  = tid + it * NT;
        int pr = t / 12, r = t % 12;               // r = ks*4 + qc
        cpa16(stg + pr * PRSTR + r * 16,
              g_v2h + (((size_t)b * 80 + pr) * NS16 + s0 + (r >> 2)) * 4 + (r & 3));
    }
#pragma unroll
    for (int it = 0; it < 2; it++) {               // 408 x 16B
        int t = tid + it * NT;
        if (t < STG_KP / 16)
            cpa16(stg + STG_V2 + t * 16, (const char*)g_kh + (size_t)s0 * SLICE_KB + t * 16);
    }
}

__global__ __launch_bounds__(NT, 2)
void mpcos_main(const float* __restrict__ v1, float* __restrict__ out)
{
    const uint32_t sb = s2u(dynsmem);
    const int tid  = threadIdx.x;
    const int w    = tid >> 5, lane = tid & 31;
    const int qrow = lane >> 2, qc = lane & 3;
    const int w5   = w % 5, mw = w / 5;            // j-tile (32 rows), m-half (32 cols)
    const int b    = blockIdx.y;
    const int i0   = blockIdx.x * I_PER;

    const float* v1b = v1 + ((size_t)b * PT1 + i0) * PD;

    // ---- v1 fp16 pair table: slot = ii*192 + s*4 + qc -> {h2(d0,d0+1), h2(d0+8,d0+9)} ----
    // STRIDED loop: I_PER*192 = 384 > NT, a single guarded store leaves slots
    // [NT,384) uninitialized (the R8 NaN bug).
    for (int t = tid; t < I_PER * 192; t += NT) {
        int ii = (t >= 192) ? 1 : 0;
        int r  = t - ii * 192;
        int s  = r >> 2, q = r & 3;
        int d0 = s * 16 + 2 * q;
        const float* vp = v1b + (size_t)ii * PD + d0;
        float2 o;
        o.x = __uint_as_float(h2pack(vp[0], vp[1]));
        o.y = __uint_as_float(h2pack(vp[8], vp[9]));
        *(float2*)(dynsmem + (size_t)t * 8) = o;
    }

    prefetch_stage(sb + V1T, b, 0, tid);
    asm volatile("cp.async.commit_group;" ::: "memory");
    prefetch_stage(sb + V1T + STGB, b, KSC, tid);
    asm volatile("cp.async.commit_group;" ::: "memory");

    float acc[2][I_PER][4][4] = {};                // [jsub][ii][nt][4]

    // stage-relative offsets
    const uint32_t aoff0 = (uint32_t)(((2 * w5 + 0) * 8 + qrow) * PRSTR + qc * 16);
    const uint32_t aoff1 = (uint32_t)(((2 * w5 + 1) * 8 + qrow) * PRSTR + qc * 16);
    const uint32_t boff  = (uint32_t)(STG_V2 + qc * 544 + (mw * 32 + qrow) * 8);

    for (int c = 0; c < NCHUNK; c++) {
        asm volatile("cp.async.wait_group 1;" ::: "memory");   // chunk c arrived
        __syncthreads();                                       // chunk c-1 fully consumed

        if (c + 2 < NCHUNK) {
            prefetch_stage(sb + V1T + ((c + 2) % NS) * STGB, b, (c + 2) * KSC, tid);
            asm volatile("cp.async.commit_group;" ::: "memory");
        }

        const char* stg = dynsmem + V1T + (c % NS) * STGB;
        const int vslot = (c * KSC) * 4 + qc;       // float2 slot base into v1 table

#pragma unroll
        for (int ks = 0; ks < KSC; ks++) {
            // A fragments: raw v2 fp16 pairs, one LDS.128 per j-subtile
            const float4 va0 = *(const float4*)(stg + aoff0 + ks * 64);
            const float4 va1 = *(const float4*)(stg + aoff1 + ks * 64);
            // v1 fp16 pairs (broadcast)
            const float2 p0 = *(const float2*)(dynsmem + (size_t)(vslot + ks * 4) * 8);
            const float2 p1 = *(const float2*)(dynsmem + (size_t)(192 + vslot + ks * 4) * 8);
            const uint32_t v0lo = __float_as_uint(p0.x), v0hi = __float_as_uint(p0.y);
            const uint32_t v1lo = __float_as_uint(p1.x), v1hi = __float_as_uint(p1.y);

            // a-frags: A[jsub][ii] = va * v1 (fp16x2 muls)
            uint32_t A0[2][4], A1[2][4];
            A0[0][0] = hmul2(__float_as_uint(va0.x), v0lo);
            A0[0][1] = hmul2(__float_as_uint(va0.y), v0lo);
            A0[0][2] = hmul2(__float_as_uint(va0.z), v0hi);
            A0[0][3] = hmul2(__float_as_uint(va0.w), v0hi);
            A0[1][0] = hmul2(__float_as_uint(va0.x), v1lo);
            A0[1][1] = hmul2(__float_as_uint(va0.y), v1lo);
            A0[1][2] = hmul2(__float_as_uint(va0.z), v1hi);
            A0[1][3] = hmul2(__float_as_uint(va0.w), v1hi);
            A1[0][0] = hmul2(__float_as_uint(va1.x), v0lo);
            A1[0][1] = hmul2(__float_as_uint(va1.y), v0lo);
            A1[0][2] = hmul2(__float_as_uint(va1.z), v0hi);
            A1[0][3] = hmul2(__float_as_uint(va1.w), v0hi);
            A1[1][0] = hmul2(__float_as_uint(va1.x), v1lo);
            A1[1][1] = hmul2(__float_as_uint(va1.y), v1lo);
            A1[1][2] = hmul2(__float_as_uint(va1.z), v1hi);
            A1[1][3] = hmul2(__float_as_uint(va1.w), v1hi);

            const char* bb = stg + boff + ks * SLICE_KB;
#pragma unroll
            for (int nt = 0; nt < 4; nt++) {
                const float2 bf = *(const float2*)(bb + nt * 64);
                const uint32_t b0 = __float_as_uint(bf.x);
                const uint32_t b1 = __float_as_uint(bf.y);
#pragma unroll
                for (int ii = 0; ii < I_PER; ii++) {
#define DO_MMA(ACC, AR)                                                         \
                    asm volatile(                                               \
                        "mma.sync.aligned.m16n8k16.row.col.f32.f16.f16.f32 "   \
                        "{%0,%1,%2,%3}, {%4,%5,%6,%7}, {%8,%9}, {%0,%1,%2,%3};"\
                        : "+f"(ACC[0]), "+f"(ACC[1]), "+f"(ACC[2]), "+f"(ACC[3])\
                        : "r"(AR[0]), "r"(AR[1]), "r"(AR[2]), "r"(AR[3]),      \
                          "r"(b0), "r"(b1))
                    DO_MMA(acc[0][ii][nt], A0[ii]);
                    DO_MMA(acc[1][ii][nt], A1[ii]);
#undef DO_MMA
                }
            }
        }
    }

    // ---- epilogue: tanh + store ----
#pragma unroll
    for (int jsub = 0; jsub < 2; jsub++) {
        const int jr = w5 * 32 + jsub * 16 + qrow;
#pragma unroll
        for (int ii = 0; ii < I_PER; ii++) {
            float* ob = out + ((size_t)(b * PT1 + i0 + ii) * PT2) * PM;
#pragma unroll
            for (int nt = 0; nt < 4; nt++) {
                const int col = mw * 32 + nt * 8 + 2 * qc;
                float2 r0, r1;
                r0.x = fast_tanh(acc[jsub][ii][nt][0]);
                r0.y = fast_tanh(acc[jsub][ii][nt][1]);
                r1.x = fast_tanh(acc[jsub][ii][nt][2]);
                r1.y = fast_tanh(acc[jsub][ii][nt][3]);
                *(float2*)(ob + (size_t)jr * PM + col)       = r0;
                *(float2*)(ob + (size_t)(jr + 8) * PM + col) = r1;
            }
        }
    }
}

extern "C" void kernel_launch(void* const* d_in, const int* in_sizes, int n_in,
                              void* d_out, int out_size)
{
    const float* v1 = nullptr;
    const float* v2 = nullptr;
    const float* kern = nullptr;
    for (int idx = 0; idx < n_in; idx++) {
        if (in_sizes[idx] == PB * PT1 * PD)      v1   = (const float*)d_in[idx];
        else if (in_sizes[idx] == PB * PT2 * PD) v2   = (const float*)d_in[idx];
        else if (in_sizes[idx] == PM * PD)       kern = (const float*)d_in[idx];
    }
    float* out = (float*)d_out;

    prep_all<<<(V2HN + KHN + 255) / 256, 256>>>(v2, kern);

    cudaFuncSetAttribute(mpcos_main, cudaFuncAttributeMaxDynamicSharedMemorySize, SMEM_TOTAL);
    dim3 grid(PT1 / I_PER, PB);   // (64, 64)
    mpcos_main<<<grid, NT, SMEM_TOTAL>>>(v1, out);
}